// round 1
// baseline (speedup 1.0000x reference)
#include <cuda_runtime.h>
#include <math.h>

// AlphaBetaFilter: B=32, T=4096, C=128, single-pass chunked linear scan.
#define BB   32
#define TT   4096
#define CC   128
#define LC   64
#define NCH  (TT / LC)          // 64 chunks per (b,c) chain

// Scratch (allocation-free): per-chunk aggregates + ready flags.
__device__ float2   g_partial[NCH * BB * CC];   // [(j*BB + b)*CC + c]
__device__ unsigned g_flag[NCH * BB];           // [j*BB + b]

__global__ void reset_flags_kernel() {
    int i = blockIdx.x * blockDim.x + threadIdx.x;
    if (i < NCH * BB) g_flag[i] = 0u;
}

__device__ __forceinline__ float sigmoid_clamped(float z) {
    float s = 1.0f / (1.0f + expf(-z));
    return fminf(fmaxf(s, 1e-4f), 1.0f - 1e-4f);
}

__global__ void __launch_bounds__(CC)
ab_filter_kernel(const float* __restrict__ x,
                 const float* __restrict__ logit_alpha,
                 const float* __restrict__ logit_beta,
                 float* __restrict__ out)
{
    const int b = blockIdx.x;   // batch
    const int j = blockIdx.y;   // chunk index (ascending linear block id -> in-order dispatch)
    const int c = threadIdx.x;  // channel

    const float av = sigmoid_clamped(logit_alpha[c]);
    const float bv = sigmoid_clamped(logit_beta[c]);

    const size_t base = ((size_t)b * TT + (size_t)j * LC) * CC + c;
    const float* xc = x   + base;
    float*       oc = out + base;

    // ---- Load chunk into registers (coalesced 512B rows, 64 independent LDGs) ----
    float xv[LC];
#pragma unroll
    for (int t = 0; t < LC; t++) xv[t] = xc[(size_t)t * CC];

    // ---- Phase 1: local scan ----
    float L, S;
    if (j == 0) {
        // chunk 0 knows the true init: L0 = x[:,0,:], slope0 = 0; write outputs now.
        L = xv[0];
        S = 0.0f;
        oc[0] = L;
#pragma unroll
        for (int t = 1; t < LC; t++) {
            float pred = L + S;
            float e = av * (xv[t] - pred);
            L = pred + e;
            S = fmaf(bv, e, S);
            oc[(size_t)t * CC] = L;
        }
    } else {
        // aggregate from zero state (recurrence is affine -> exact decomposition)
        L = 0.0f;
        S = 0.0f;
#pragma unroll
        for (int t = 0; t < LC; t++) {
            float pred = L + S;
            float e = av * (xv[t] - pred);
            L = pred + e;
            S = fmaf(bv, e, S);
        }
    }

    // ---- Publish aggregate, then release flag ----
    g_partial[((size_t)j * BB + b) * CC + c] = make_float2(L, S);
    __threadfence();
    __syncthreads();
    if (c == 0) {
        unsigned one = 1u;
        asm volatile("st.release.gpu.b32 [%0], %1;"
                     :: "l"(&g_flag[j * BB + b]), "r"(one) : "memory");
    }
    if (j == 0) return;

    // ---- Lookback: wait for all predecessor aggregates (published before any spin) ----
    if (c < j) {
        const unsigned* fp = &g_flag[c * BB + b];
        unsigned v;
        do {
            asm volatile("ld.acquire.gpu.b32 %0, [%1];"
                         : "=r"(v) : "l"(fp) : "memory");
        } while (v == 0u);
    }
    __syncthreads();

    // A = M^LC via repeated squaring; M = [[1-a, 1-a], [-a*b, 1-a*b]]
    float A00 = 1.0f - av, A01 = 1.0f - av;
    float A10 = -av * bv,  A11 = 1.0f - av * bv;
#pragma unroll
    for (int p = 0; p < 6; p++) {   // 2^6 = 64 = LC
        float n00 = fmaf(A00, A00, A01 * A10);
        float n01 = fmaf(A00, A01, A01 * A11);
        float n10 = fmaf(A10, A00, A11 * A10);
        float n11 = fmaf(A10, A01, A11 * A11);
        A00 = n00; A01 = n01; A10 = n10; A11 = n11;
    }

    // Horner combine: state entering chunk j = ((p0*A + p1)*A + p2)...*A + p_{j-1}
    const float2* pp = &g_partial[(size_t)b * CC + c];   // stride BB*CC float2 per chunk
    float2 p0 = pp[0];
    float sl = p0.x, ss = p0.y;
    for (int k = 1; k < j; k += 8) {
        float2 buf[8];
#pragma unroll
        for (int i = 0; i < 8; i++) {
            int kk = k + i;
            buf[i] = (kk < j) ? pp[(size_t)kk * (BB * CC)] : make_float2(0.0f, 0.0f);
        }
#pragma unroll
        for (int i = 0; i < 8; i++) {
            int kk = k + i;
            if (kk < j) {
                float nl = fmaf(A00, sl, fmaf(A01, ss, buf[i].x));
                float ns = fmaf(A10, sl, fmaf(A11, ss, buf[i].y));
                sl = nl; ss = ns;
            }
        }
    }

    // ---- Phase 2: rescan with correct incoming state, write outputs ----
    L = sl; S = ss;
#pragma unroll
    for (int t = 0; t < LC; t++) {
        float pred = L + S;
        float e = av * (xv[t] - pred);
        L = pred + e;
        S = fmaf(bv, e, S);
        oc[(size_t)t * CC] = L;
    }
}

extern "C" void kernel_launch(void* const* d_in, const int* in_sizes, int n_in,
                              void* d_out, int out_size)
{
    const float* x  = (const float*)d_in[0];
    const float* la = (const float*)d_in[1];
    const float* lb = (const float*)d_in[2];
    float* out = (float*)d_out;

    reset_flags_kernel<<<(NCH * BB + 255) / 256, 256>>>();

    dim3 grid(BB, NCH);
    ab_filter_kernel<<<grid, CC>>>(x, la, lb, out);
}

// round 4
// speedup vs baseline: 1.0462x; 1.0462x over previous
#include <cuda_runtime.h>
#include <math.h>

// AlphaBetaFilter: B=32, T=4096, C=128, single-pass chunked linear scan.
// x staged in SMEM (no register spills), decoupled-lookback across 64 chunks.
#define BB   32
#define TT   4096
#define CC   128
#define LC   64
#define NCH  (TT / LC)          // 64 chunks per (b,c) chain

// Scratch (allocation-free): per-chunk aggregates + ready flags.
__device__ float2   g_partial[NCH * BB * CC];   // [(j*BB + b)*CC + c]
__device__ unsigned g_flag[NCH * BB];           // [j*BB + b]

__global__ void reset_flags_kernel() {
    int i = blockIdx.x * blockDim.x + threadIdx.x;
    if (i < NCH * BB) g_flag[i] = 0u;
}

__device__ __forceinline__ float sigmoid_clamped(float z) {
    float s = 1.0f / (1.0f + expf(-z));
    return fminf(fmaxf(s, 1e-4f), 1.0f - 1e-4f);
}

__global__ void __launch_bounds__(CC, 7)
ab_filter_kernel(const float* __restrict__ x,
                 const float* __restrict__ logit_alpha,
                 const float* __restrict__ logit_beta,
                 float* __restrict__ out)
{
    __shared__ float sx[LC * CC];   // 32 KB: one chunk, row-major [t][c]

    const int b = blockIdx.x;   // batch
    const int j = blockIdx.y;   // chunk index (ascending linear id -> in-order dispatch)
    const int c = threadIdx.x;  // channel

    const float av = sigmoid_clamped(logit_alpha[c]);
    const float bv = sigmoid_clamped(logit_beta[c]);

    const size_t base = ((size_t)b * TT + (size_t)j * LC) * CC;

    // ---- Stage chunk into SMEM: 2048 float4, 16 per thread, fully coalesced ----
    {
        const float4* xg = (const float4*)(x + base);
        float4* sv = (float4*)sx;
#pragma unroll
        for (int i = 0; i < (LC * CC / 4) / CC; i++)       // 16 iters
            sv[i * CC + c] = xg[i * CC + c];
    }
    __syncthreads();

    // ---- Phase 1: local scan (aggregate) ----
    float L, S;
    if (j == 0) {
        // chunk 0 knows the true init: L0 = x[:,0,:], slope0 = 0
        L = sx[c];
        S = 0.0f;
#pragma unroll
        for (int t = 1; t < LC; t++) {
            float pred = L + S;
            float e = av * (sx[t * CC + c] - pred);
            L = pred + e;
            S = fmaf(bv, e, S);
        }
    } else {
        // aggregate from zero state (recurrence is affine -> exact decomposition)
        L = 0.0f;
        S = 0.0f;
#pragma unroll
        for (int t = 0; t < LC; t++) {
            float pred = L + S;
            float e = av * (sx[t * CC + c] - pred);
            L = pred + e;
            S = fmaf(bv, e, S);
        }
    }

    // ---- Publish aggregate, then release flag ----
    g_partial[((size_t)j * BB + b) * CC + c] = make_float2(L, S);
    __threadfence();
    __syncthreads();
    if (c == 0) {
        unsigned one = 1u;
        asm volatile("st.release.gpu.b32 [%0], %1;"
                     :: "l"(&g_flag[j * BB + b]), "r"(one) : "memory");
    }

    float sl = 0.0f, ss = 0.0f;   // incoming state for this chunk
    if (j > 0) {
        // ---- Lookback: wait for all predecessor aggregates ----
        if (c < j) {
            const unsigned* fp = &g_flag[c * BB + b];
            unsigned v;
            do {
                asm volatile("ld.acquire.gpu.b32 %0, [%1];"
                             : "=r"(v) : "l"(fp) : "memory");
            } while (v == 0u);
        }
        __syncthreads();

        // A = M^LC via repeated squaring; M = [[1-a, 1-a], [-a*b, 1-a*b]]
        float A00 = 1.0f - av, A01 = 1.0f - av;
        float A10 = -av * bv,  A11 = 1.0f - av * bv;
#pragma unroll
        for (int p = 0; p < 6; p++) {   // 2^6 = 64 = LC
            float n00 = fmaf(A00, A00, A01 * A10);
            float n01 = fmaf(A00, A01, A01 * A11);
            float n10 = fmaf(A10, A00, A11 * A10);
            float n11 = fmaf(A10, A01, A11 * A11);
            A00 = n00; A01 = n01; A10 = n10; A11 = n11;
        }

        // Horner combine over predecessor aggregates (batched loads, L2-hot)
        const float2* pp = &g_partial[(size_t)b * CC + c];  // stride BB*CC float2/chunk
        float2 p0 = pp[0];
        sl = p0.x; ss = p0.y;
        for (int k = 1; k < j; k += 8) {
            float2 buf[8];
#pragma unroll
            for (int i = 0; i < 8; i++) {
                int kk = k + i;
                buf[i] = (kk < j) ? pp[(size_t)kk * (BB * CC)] : make_float2(0.0f, 0.0f);
            }
#pragma unroll
            for (int i = 0; i < 8; i++) {
                int kk = k + i;
                if (kk < j) {
                    float nl = fmaf(A00, sl, fmaf(A01, ss, buf[i].x));
                    float ns = fmaf(A10, sl, fmaf(A11, ss, buf[i].y));
                    sl = nl; ss = ns;
                }
            }
        }
    }

    // ---- Phase 2: rescan from correct incoming state, write outputs ----
    float* oc = out + base + c;
    if (j == 0) {
        L = sx[c];
        S = 0.0f;
        oc[0] = L;
#pragma unroll
        for (int t = 1; t < LC; t++) {
            float pred = L + S;
            float e = av * (sx[t * CC + c] - pred);
            L = pred + e;
            S = fmaf(bv, e, S);
            oc[(size_t)t * CC] = L;
        }
    } else {
        L = sl; S = ss;
#pragma unroll
        for (int t = 0; t < LC; t++) {
            float pred = L + S;
            float e = av * (sx[t * CC + c] - pred);
            L = pred + e;
            S = fmaf(bv, e, S);
            oc[(size_t)t * CC] = L;
        }
    }
}

extern "C" void kernel_launch(void* const* d_in, const int* in_sizes, int n_in,
                              void* d_out, int out_size)
{
    const float* x  = (const float*)d_in[0];
    const float* la = (const float*)d_in[1];
    const float* lb = (const float*)d_in[2];
    float* out = (float*)d_out;

    reset_flags_kernel<<<(NCH * BB + 255) / 256, 256>>>();

    dim3 grid(BB, NCH);
    ab_filter_kernel<<<grid, CC>>>(x, la, lb, out);
}

// round 7
// speedup vs baseline: 1.0843x; 1.0364x over previous
#include <cuda_runtime.h>
#include <math.h>

// AlphaBetaFilter: B=32, T=4096, C=128. Chunked linear scan, decoupled lookback.
// Stride-4 scan: dependent chain = 2 FMA per 4 timesteps.
#define BB   32
#define TT   4096
#define CC   128
#define LC   64
#define NCH  (TT / LC)          // 64 chunks per (b,c) chain
#define NG   (LC / 4)           // 16 groups of 4 timesteps

__device__ float2   g_partial[NCH * BB * CC];   // [(j*BB + b)*CC + c]
__device__ unsigned g_flag[NCH * BB];           // [j*BB + b]

__global__ void reset_flags_kernel() {
    int i = blockIdx.x * blockDim.x + threadIdx.x;
    if (i < NCH * BB) g_flag[i] = 0u;
}

__device__ __forceinline__ float sigmoid_clamped(float z) {
    float s = 1.0f / (1.0f + expf(-z));
    return fminf(fmaxf(s, 1e-4f), 1.0f - 1e-4f);
}

struct m22 { float a00, a01, a10, a11; };
__device__ __forceinline__ m22 mmul(m22 P, m22 Q) {
    m22 r;
    r.a00 = fmaf(P.a00, Q.a00, P.a01 * Q.a10);
    r.a01 = fmaf(P.a00, Q.a01, P.a01 * Q.a11);
    r.a10 = fmaf(P.a10, Q.a00, P.a11 * Q.a10);
    r.a11 = fmaf(P.a10, Q.a01, P.a11 * Q.a11);
    return r;
}

__global__ void __launch_bounds__(CC, 6)
ab_filter_kernel(const float* __restrict__ x,
                 const float* __restrict__ logit_alpha,
                 const float* __restrict__ logit_beta,
                 float* __restrict__ out)
{
    __shared__ float sx[LC * CC];   // 32 KB, row-major [t][c]

    const int b = blockIdx.x;
    const int j = blockIdx.y;
    const int c = threadIdx.x;

    const float av = sigmoid_clamped(logit_alpha[c]);
    const float bv = sigmoid_clamped(logit_beta[c]);
    const float abp = av * bv;

    // M = [[1-a, 1-a], [-ab, 1-ab]], u = [a, ab]
    m22 M1 = {1.0f - av, 1.0f - av, -abp, 1.0f - abp};
    m22 M2 = mmul(M1, M1);
    m22 M3 = mmul(M2, M1);
    m22 M4 = mmul(M2, M2);
    // v_i = M^i u
    float v0x = av,  v0y = abp;
    float v1x = fmaf(M1.a00, v0x, M1.a01 * v0y), v1y = fmaf(M1.a10, v0x, M1.a11 * v0y);
    float v2x = fmaf(M1.a00, v1x, M1.a01 * v1y), v2y = fmaf(M1.a10, v1x, M1.a11 * v1y);
    float v3x = fmaf(M1.a00, v2x, M1.a01 * v2y), v3y = fmaf(M1.a10, v2x, M1.a11 * v2y);

    const size_t base = ((size_t)b * TT + (size_t)j * LC) * CC;

    // ---- Stage chunk into SMEM (16 float4/thread, coalesced) ----
    {
        const float4* xg = (const float4*)(x + base);
        float4* sv = (float4*)sx;
#pragma unroll
        for (int i = 0; i < 16; i++)
            sv[i * CC + c] = xg[i * CC + c];
    }
    __syncthreads();

    // ---- Phase 1: aggregate via stride-4 recurrence ----
    // Chunk 0 init trick: s_{-1} = (x_0, 0) makes step t=0 reproduce L_0 = x_0 exactly.
    float L = (j == 0) ? sx[c] : 0.0f;
    float S = 0.0f;
#pragma unroll
    for (int g = 0; g < NG; g++) {
        float x0 = sx[(4 * g + 0) * CC + c];
        float x1 = sx[(4 * g + 1) * CC + c];
        float x2 = sx[(4 * g + 2) * CC + c];
        float x3 = sx[(4 * g + 3) * CC + c];
        float cL = fmaf(v3x, x0, fmaf(v2x, x1, fmaf(v1x, x2, v0x * x3)));
        float cS = fmaf(v3y, x0, fmaf(v2y, x1, fmaf(v1y, x2, v0y * x3)));
        float Ln = fmaf(M4.a00, L, fmaf(M4.a01, S, cL));
        float Sn = fmaf(M4.a10, L, fmaf(M4.a11, S, cS));
        L = Ln; S = Sn;
    }

    // ---- Publish aggregate, then release flag ----
    g_partial[((size_t)j * BB + b) * CC + c] = make_float2(L, S);
    __threadfence();
    __syncthreads();
    if (c == 0) {
        unsigned one = 1u;
        asm volatile("st.release.gpu.b32 [%0], %1;"
                     :: "l"(&g_flag[j * BB + b]), "r"(one) : "memory");
    }

    // ---- Lookback: incoming state for this chunk ----
    float sl, ss;
    if (j == 0) {
        sl = sx[c]; ss = 0.0f;
    } else {
        // Low-traffic wait: one probe, then nanosleep backoff.
        if (c < j) {
            const unsigned* fp = &g_flag[c * BB + b];
            unsigned v;
            asm volatile("ld.acquire.gpu.b32 %0, [%1];" : "=r"(v) : "l"(fp) : "memory");
            while (v == 0u) {
                __nanosleep(200);
                asm volatile("ld.acquire.gpu.b32 %0, [%1];" : "=r"(v) : "l"(fp) : "memory");
            }
        }
        __syncthreads();

        // A1 = M^64 (4 squarings of M4), A2..A4 = higher powers for grouped Horner
        m22 A1 = M4;
        A1 = mmul(A1, A1); A1 = mmul(A1, A1); A1 = mmul(A1, A1); A1 = mmul(A1, A1);
        m22 A2 = mmul(A1, A1);
        m22 A3 = mmul(A2, A1);
        m22 A4 = mmul(A2, A2);

        const float2* pp = &g_partial[(size_t)b * CC + c];
        const size_t ST = (size_t)BB * CC;   // float2 stride per chunk

        float rl = 0.0f, rs = 0.0f;
        int k = 0;
        const int head = j & 3;              // make remaining count divisible by 4
        for (int i = 0; i < head; i++, k++) {
            float2 p = pp[(size_t)k * ST];
            float nl = fmaf(A1.a00, rl, fmaf(A1.a01, rs, p.x));
            float ns = fmaf(A1.a10, rl, fmaf(A1.a11, rs, p.y));
            rl = nl; rs = ns;
        }
        // Superblocks of 8 terms (2 groups of 4), loads batched for MLP.
        while (k < j) {
            int n = j - k; if (n > 8) n = 8;     // n is a multiple of 4
            float2 q[8];
#pragma unroll
            for (int i = 0; i < 8; i++)
                if (i < n) q[i] = pp[(size_t)(k + i) * ST];
#pragma unroll
            for (int i = 0; i < 8; i += 4) {
                if (i < n) {
                    float gl = fmaf(A3.a00, q[i].x, fmaf(A3.a01, q[i].y,
                               fmaf(A2.a00, q[i+1].x, fmaf(A2.a01, q[i+1].y,
                               fmaf(A1.a00, q[i+2].x, fmaf(A1.a01, q[i+2].y, q[i+3].x))))));
                    float gs = fmaf(A3.a10, q[i].x, fmaf(A3.a11, q[i].y,
                               fmaf(A2.a10, q[i+1].x, fmaf(A2.a11, q[i+1].y,
                               fmaf(A1.a10, q[i+2].x, fmaf(A1.a11, q[i+2].y, q[i+3].y))))));
                    float nl = fmaf(A4.a00, rl, fmaf(A4.a01, rs, gl));
                    float ns = fmaf(A4.a10, rl, fmaf(A4.a11, rs, gs));
                    rl = nl; rs = ns;
                }
            }
            k += n;
        }
        sl = rl; ss = rs;
    }

    // ---- Phase 2: stride-4 rescan with outputs (intermediates off-chain) ----
    L = sl; S = ss;
    float* oc = out + base + c;
#pragma unroll
    for (int g = 0; g < NG; g++) {
        float x0 = sx[(4 * g + 0) * CC + c];
        float x1 = sx[(4 * g + 1) * CC + c];
        float x2 = sx[(4 * g + 2) * CC + c];
        float x3 = sx[(4 * g + 3) * CC + c];

        float o0 = fmaf(M1.a00, L, fmaf(M1.a01, S, v0x * x0));
        float o1 = fmaf(M2.a00, L, fmaf(M2.a01, S, fmaf(v1x, x0, v0x * x1)));
        float o2 = fmaf(M3.a00, L, fmaf(M3.a01, S,
                   fmaf(v2x, x0, fmaf(v1x, x1, v0x * x2))));
        float cL = fmaf(v3x, x0, fmaf(v2x, x1, fmaf(v1x, x2, v0x * x3)));
        float cS = fmaf(v3y, x0, fmaf(v2y, x1, fmaf(v1y, x2, v0y * x3)));
        float o3 = fmaf(M4.a00, L, fmaf(M4.a01, S, cL));
        float Sn = fmaf(M4.a10, L, fmaf(M4.a11, S, cS));

        oc[(size_t)(4 * g + 0) * CC] = o0;
        oc[(size_t)(4 * g + 1) * CC] = o1;
        oc[(size_t)(4 * g + 2) * CC] = o2;
        oc[(size_t)(4 * g + 3) * CC] = o3;
        L = o3; S = Sn;
    }
}

extern "C" void kernel_launch(void* const* d_in, const int* in_sizes, int n_in,
                              void* d_out, int out_size)
{
    const float* x  = (const float*)d_in[0];
    const float* la = (const float*)d_in[1];
    const float* lb = (const float*)d_in[2];
    float* out = (float*)d_out;

    reset_flags_kernel<<<(NCH * BB + 255) / 256, 256>>>();

    dim3 grid(BB, NCH);
    ab_filter_kernel<<<grid, CC>>>(x, la, lb, out);
}

// round 8
// speedup vs baseline: 1.3809x; 1.2735x over previous
#include <cuda_runtime.h>
#include <math.h>

// AlphaBetaFilter: B=32, T=4096, C=128.
// 3-kernel chunked linear scan: aggregate -> prefix -> rescan.
// No intra-kernel sync; kernel boundaries are the global barriers.
#define BB   32
#define TT   4096
#define CC   128
#define LC   64
#define NCH  (TT / LC)          // 64 chunks per (b,c) chain
#define NG   (LC / 4)           // 16 groups of 4 timesteps

__device__ float2 g_partial[NCH * BB * CC];   // chunk aggregates  [(j*BB+b)*CC+c]
__device__ float2 g_prefix [NCH * BB * CC];   // incoming state for chunk j (j>=1)

__device__ __forceinline__ float sigmoid_clamped(float z) {
    float s = 1.0f / (1.0f + expf(-z));
    return fminf(fmaxf(s, 1e-4f), 1.0f - 1e-4f);
}

struct m22 { float a00, a01, a10, a11; };
__device__ __forceinline__ m22 mmul(m22 P, m22 Q) {
    m22 r;
    r.a00 = fmaf(P.a00, Q.a00, P.a01 * Q.a10);
    r.a01 = fmaf(P.a00, Q.a01, P.a01 * Q.a11);
    r.a10 = fmaf(P.a10, Q.a00, P.a11 * Q.a10);
    r.a11 = fmaf(P.a10, Q.a01, P.a11 * Q.a11);
    return r;
}

struct Coef {
    m22 M1, M2, M3, M4;
    float v0x, v0y, v1x, v1y, v2x, v2y, v3x, v3y;
};

__device__ __forceinline__ Coef make_coef(float av, float bv) {
    Coef k;
    float abp = av * bv;
    k.M1 = {1.0f - av, 1.0f - av, -abp, 1.0f - abp};
    k.M2 = mmul(k.M1, k.M1);
    k.M3 = mmul(k.M2, k.M1);
    k.M4 = mmul(k.M2, k.M2);
    k.v0x = av;  k.v0y = abp;
    k.v1x = fmaf(k.M1.a00, k.v0x, k.M1.a01 * k.v0y);
    k.v1y = fmaf(k.M1.a10, k.v0x, k.M1.a11 * k.v0y);
    k.v2x = fmaf(k.M1.a00, k.v1x, k.M1.a01 * k.v1y);
    k.v2y = fmaf(k.M1.a10, k.v1x, k.M1.a11 * k.v1y);
    k.v3x = fmaf(k.M1.a00, k.v2x, k.M1.a01 * k.v2y);
    k.v3y = fmaf(k.M1.a10, k.v2x, k.M1.a11 * k.v2y);
    return k;
}

// ---------------- k1: per-chunk aggregates (pure streaming) ----------------
__global__ void __launch_bounds__(CC, 7)
k1_aggregate(const float* __restrict__ x,
             const float* __restrict__ logit_alpha,
             const float* __restrict__ logit_beta)
{
    __shared__ float sx[LC * CC];
    const int b = blockIdx.x, j = blockIdx.y, c = threadIdx.x;

    const float av = sigmoid_clamped(logit_alpha[c]);
    const float bv = sigmoid_clamped(logit_beta[c]);
    const Coef K = make_coef(av, bv);

    const size_t base = ((size_t)b * TT + (size_t)j * LC) * CC;
    {
        const float4* xg = (const float4*)(x + base);
        float4* sv = (float4*)sx;
#pragma unroll
        for (int i = 0; i < 16; i++) sv[i * CC + c] = xg[i * CC + c];
    }
    __syncthreads();

    // Chunk 0 init trick: starting state (x0, 0) makes step 0 reproduce L0=x0.
    float L = (j == 0) ? sx[c] : 0.0f;
    float S = 0.0f;
#pragma unroll
    for (int g = 0; g < NG; g++) {
        float x0 = sx[(4 * g + 0) * CC + c];
        float x1 = sx[(4 * g + 1) * CC + c];
        float x2 = sx[(4 * g + 2) * CC + c];
        float x3 = sx[(4 * g + 3) * CC + c];
        float cL = fmaf(K.v3x, x0, fmaf(K.v2x, x1, fmaf(K.v1x, x2, K.v0x * x3)));
        float cS = fmaf(K.v3y, x0, fmaf(K.v2y, x1, fmaf(K.v1y, x2, K.v0y * x3)));
        float Ln = fmaf(K.M4.a00, L, fmaf(K.M4.a01, S, cL));
        float Sn = fmaf(K.M4.a10, L, fmaf(K.M4.a11, S, cS));
        L = Ln; S = Sn;
    }
    g_partial[((size_t)j * BB + b) * CC + c] = make_float2(L, S);
}

// ---------------- k2: prefix over chunk aggregates (L2-hot, tiny) ----------
__global__ void __launch_bounds__(CC)
k2_prefix(const float* __restrict__ logit_alpha,
          const float* __restrict__ logit_beta)
{
    const int b = blockIdx.x, c = threadIdx.x;
    const float av = sigmoid_clamped(logit_alpha[c]);
    const float bv = sigmoid_clamped(logit_beta[c]);
    const float abp = av * bv;

    m22 A = {1.0f - av, 1.0f - av, -abp, 1.0f - abp};   // M
    A = mmul(A, A); A = mmul(A, A);                     // M^4
    A = mmul(A, A); A = mmul(A, A);
    A = mmul(A, A); A = mmul(A, A);                     // M^64

    const size_t ST = (size_t)BB * CC;
    const float2* pp = &g_partial[(size_t)b * CC + c];
    float2*       pr = &g_prefix [(size_t)b * CC + c];

    float2 s = pp[0];                 // state after chunk 0
    for (int j = 1; j < NCH; j += 8) {
        float2 q[8];
#pragma unroll
        for (int i = 0; i < 8; i++) {
            int jj = j + i;
            q[i] = (jj < NCH) ? pp[(size_t)jj * ST] : make_float2(0.0f, 0.0f);
        }
#pragma unroll
        for (int i = 0; i < 8; i++) {
            int jj = j + i;
            if (jj < NCH) {
                pr[(size_t)jj * ST] = s;   // incoming state for chunk jj
                float nl = fmaf(A.a00, s.x, fmaf(A.a01, s.y, q[i].x));
                float ns = fmaf(A.a10, s.x, fmaf(A.a11, s.y, q[i].y));
                s.x = nl; s.y = ns;
            }
        }
    }
}

// ---------------- k3: rescan + write outputs (streaming stores) ------------
__global__ void __launch_bounds__(CC, 7)
k3_rescan(const float* __restrict__ x,
          const float* __restrict__ logit_alpha,
          const float* __restrict__ logit_beta,
          float* __restrict__ out)
{
    __shared__ float sx[LC * CC];
    const int b = blockIdx.x, j = blockIdx.y, c = threadIdx.x;

    const float av = sigmoid_clamped(logit_alpha[c]);
    const float bv = sigmoid_clamped(logit_beta[c]);
    const Coef K = make_coef(av, bv);

    const size_t base = ((size_t)b * TT + (size_t)j * LC) * CC;
    {
        const float4* xg = (const float4*)(x + base);
        float4* sv = (float4*)sx;
#pragma unroll
        for (int i = 0; i < 16; i++) sv[i * CC + c] = xg[i * CC + c];
    }
    __syncthreads();

    float L, S;
    if (j == 0) {
        L = sx[c]; S = 0.0f;            // init trick
    } else {
        float2 pr = g_prefix[((size_t)j * BB + b) * CC + c];
        L = pr.x; S = pr.y;
    }

    float* oc = out + base + c;
#pragma unroll
    for (int g = 0; g < NG; g++) {
        float x0 = sx[(4 * g + 0) * CC + c];
        float x1 = sx[(4 * g + 1) * CC + c];
        float x2 = sx[(4 * g + 2) * CC + c];
        float x3 = sx[(4 * g + 3) * CC + c];

        float o0 = fmaf(K.M1.a00, L, fmaf(K.M1.a01, S, K.v0x * x0));
        float o1 = fmaf(K.M2.a00, L, fmaf(K.M2.a01, S, fmaf(K.v1x, x0, K.v0x * x1)));
        float o2 = fmaf(K.M3.a00, L, fmaf(K.M3.a01, S,
                   fmaf(K.v2x, x0, fmaf(K.v1x, x1, K.v0x * x2))));
        float cL = fmaf(K.v3x, x0, fmaf(K.v2x, x1, fmaf(K.v1x, x2, K.v0x * x3)));
        float cS = fmaf(K.v3y, x0, fmaf(K.v2y, x1, fmaf(K.v1y, x2, K.v0y * x3)));
        float o3 = fmaf(K.M4.a00, L, fmaf(K.M4.a01, S, cL));
        float Sn = fmaf(K.M4.a10, L, fmaf(K.M4.a11, S, cS));

        // streaming stores: don't evict L2-resident x
        __stcs(oc + (size_t)(4 * g + 0) * CC, o0);
        __stcs(oc + (size_t)(4 * g + 1) * CC, o1);
        __stcs(oc + (size_t)(4 * g + 2) * CC, o2);
        __stcs(oc + (size_t)(4 * g + 3) * CC, o3);
        L = o3; S = Sn;
    }
}

extern "C" void kernel_launch(void* const* d_in, const int* in_sizes, int n_in,
                              void* d_out, int out_size)
{
    const float* x  = (const float*)d_in[0];
    const float* la = (const float*)d_in[1];
    const float* lb = (const float*)d_in[2];
    float* out = (float*)d_out;

    dim3 grid(BB, NCH);
    k1_aggregate<<<grid, CC>>>(x, la, lb);
    k2_prefix<<<BB, CC>>>(la, lb);
    k3_rescan<<<grid, CC>>>(x, la, lb, out);
}

// round 9
// speedup vs baseline: 1.7293x; 1.2523x over previous
#include <cuda_runtime.h>
#include <math.h>

// AlphaBetaFilter: B=32, T=4096, C=128.
// Two-kernel chunked linear scan: aggregate -> (fused prefix + rescan).
// No smem: x streams through registers, per-warp loads are coalesced 128B lines.
#define BB   32
#define TT   4096
#define CC   128
#define LC   64
#define NCH  (TT / LC)          // 64 chunks per (b,c) chain

__device__ float2 g_partial[NCH * BB * CC];   // chunk aggregates [(j*BB+b)*CC+c]

__device__ __forceinline__ float sigmoid_clamped(float z) {
    float s = 1.0f / (1.0f + expf(-z));
    return fminf(fmaxf(s, 1e-4f), 1.0f - 1e-4f);
}

struct m22 { float a00, a01, a10, a11; };
__device__ __forceinline__ m22 mmul(m22 P, m22 Q) {
    m22 r;
    r.a00 = fmaf(P.a00, Q.a00, P.a01 * Q.a10);
    r.a01 = fmaf(P.a00, Q.a01, P.a01 * Q.a11);
    r.a10 = fmaf(P.a10, Q.a00, P.a11 * Q.a10);
    r.a11 = fmaf(P.a10, Q.a01, P.a11 * Q.a11);
    return r;
}

struct Coef {
    m22 M1, M2, M3, M4;
    float v0x, v0y, v1x, v1y, v2x, v2y, v3x, v3y;
};

__device__ __forceinline__ Coef make_coef(float av, float bv) {
    Coef k;
    float abp = av * bv;
    k.M1 = {1.0f - av, 1.0f - av, -abp, 1.0f - abp};
    k.M2 = mmul(k.M1, k.M1);
    k.M3 = mmul(k.M2, k.M1);
    k.M4 = mmul(k.M2, k.M2);
    k.v0x = av;  k.v0y = abp;
    k.v1x = fmaf(k.M1.a00, k.v0x, k.M1.a01 * k.v0y);
    k.v1y = fmaf(k.M1.a10, k.v0x, k.M1.a11 * k.v0y);
    k.v2x = fmaf(k.M1.a00, k.v1x, k.M1.a01 * k.v1y);
    k.v2y = fmaf(k.M1.a10, k.v1x, k.M1.a11 * k.v1y);
    k.v3x = fmaf(k.M1.a00, k.v2x, k.M1.a01 * k.v2y);
    k.v3y = fmaf(k.M1.a10, k.v2x, k.M1.a11 * k.v2y);
    return k;
}

// advance state by 4 timesteps (2-FMA dependent chain; conv terms off-chain)
__device__ __forceinline__ void step4(const Coef& K, float& L, float& S,
                                      float x0, float x1, float x2, float x3) {
    float cL = fmaf(K.v3x, x0, fmaf(K.v2x, x1, fmaf(K.v1x, x2, K.v0x * x3)));
    float cS = fmaf(K.v3y, x0, fmaf(K.v2y, x1, fmaf(K.v1y, x2, K.v0y * x3)));
    float Ln = fmaf(K.M4.a00, L, fmaf(K.M4.a01, S, cL));
    float Sn = fmaf(K.M4.a10, L, fmaf(K.M4.a11, S, cS));
    L = Ln; S = Sn;
}

// ---------------- k1: per-chunk aggregates (pure register streaming) -------
__global__ void __launch_bounds__(CC)
k1_aggregate(const float* __restrict__ x,
             const float* __restrict__ logit_alpha,
             const float* __restrict__ logit_beta)
{
    const int b = blockIdx.x, j = blockIdx.y, c = threadIdx.x;

    const float av = sigmoid_clamped(logit_alpha[c]);
    const float bv = sigmoid_clamped(logit_beta[c]);
    const Coef K = make_coef(av, bv);

    const float* xc = x + ((size_t)b * TT + (size_t)j * LC) * CC + c;

    float cur[8], nxt[8];
#pragma unroll
    for (int i = 0; i < 8; i++) cur[i] = xc[(size_t)i * CC];

    // Chunk 0 init trick: starting state (x0, 0) reproduces L0 = x0 at step 0.
    float L = (j == 0) ? cur[0] : 0.0f;
    float S = 0.0f;

#pragma unroll
    for (int g = 0; g < 8; g++) {
        if (g < 7) {
#pragma unroll
            for (int i = 0; i < 8; i++)
                nxt[i] = xc[(size_t)(8 * g + 8 + i) * CC];
        }
        step4(K, L, S, cur[0], cur[1], cur[2], cur[3]);
        step4(K, L, S, cur[4], cur[5], cur[6], cur[7]);
        if (g < 7) {
#pragma unroll
            for (int i = 0; i < 8; i++) cur[i] = nxt[i];
        }
    }
    g_partial[((size_t)j * BB + b) * CC + c] = make_float2(L, S);
}

// ---------------- k3: fused prefix (Horner over aggregates) + rescan -------
__global__ void __launch_bounds__(CC)
k3_rescan(const float* __restrict__ x,
          const float* __restrict__ logit_alpha,
          const float* __restrict__ logit_beta,
          float* __restrict__ out)
{
    const int b = blockIdx.x, j = blockIdx.y, c = threadIdx.x;

    const float av = sigmoid_clamped(logit_alpha[c]);
    const float bv = sigmoid_clamped(logit_beta[c]);
    const Coef K = make_coef(av, bv);

    const size_t base = ((size_t)b * TT + (size_t)j * LC) * CC + c;
    const float* xc = x + base;
    float*       oc = out + base;

    // Kick off the first x batch before the Horner chain (independent work).
    float cur[8], nxt[8];
#pragma unroll
    for (int i = 0; i < 8; i++) cur[i] = xc[(size_t)i * CC];

    // Incoming state for this chunk: Horner over predecessor aggregates.
    float L, S;
    if (j == 0) {
        L = cur[0]; S = 0.0f;          // init trick
    } else {
        m22 A = K.M4;                  // M^4
        A = mmul(A, A); A = mmul(A, A);
        A = mmul(A, A); A = mmul(A, A);   // M^64

        const float2* pp = &g_partial[(size_t)b * CC + c];
        const size_t ST = (size_t)BB * CC;

        float2 p0 = pp[0];
        float rl = p0.x, rs = p0.y;
        for (int k = 1; k < j; k += 8) {
            float2 q[8];
#pragma unroll
            for (int i = 0; i < 8; i++) {
                int kk = k + i;
                if (kk < j) q[i] = pp[(size_t)kk * ST];
            }
#pragma unroll
            for (int i = 0; i < 8; i++) {
                int kk = k + i;
                if (kk < j) {
                    float nl = fmaf(A.a00, rl, fmaf(A.a01, rs, q[i].x));
                    float ns = fmaf(A.a10, rl, fmaf(A.a11, rs, q[i].y));
                    rl = nl; rs = ns;
                }
            }
        }
        L = rl; S = rs;
    }

    // Stream the chunk: 8 groups of 8 timesteps, outputs off-chain.
#pragma unroll
    for (int g = 0; g < 8; g++) {
        if (g < 7) {
#pragma unroll
            for (int i = 0; i < 8; i++)
                nxt[i] = xc[(size_t)(8 * g + 8 + i) * CC];
        }
#pragma unroll
        for (int h = 0; h < 2; h++) {
            float x0 = cur[4 * h + 0], x1 = cur[4 * h + 1];
            float x2 = cur[4 * h + 2], x3 = cur[4 * h + 3];

            float o0 = fmaf(K.M1.a00, L, fmaf(K.M1.a01, S, K.v0x * x0));
            float o1 = fmaf(K.M2.a00, L, fmaf(K.M2.a01, S,
                       fmaf(K.v1x, x0, K.v0x * x1)));
            float o2 = fmaf(K.M3.a00, L, fmaf(K.M3.a01, S,
                       fmaf(K.v2x, x0, fmaf(K.v1x, x1, K.v0x * x2))));
            float cL = fmaf(K.v3x, x0, fmaf(K.v2x, x1, fmaf(K.v1x, x2, K.v0x * x3)));
            float cS = fmaf(K.v3y, x0, fmaf(K.v2y, x1, fmaf(K.v1y, x2, K.v0y * x3)));
            float o3 = fmaf(K.M4.a00, L, fmaf(K.M4.a01, S, cL));
            float Sn = fmaf(K.M4.a10, L, fmaf(K.M4.a11, S, cS));

            const size_t t0 = (size_t)(8 * g + 4 * h) * CC;
            __stcs(oc + t0 + 0 * CC, o0);
            __stcs(oc + t0 + 1 * CC, o1);
            __stcs(oc + t0 + 2 * CC, o2);
            __stcs(oc + t0 + 3 * CC, o3);
            L = o3; S = Sn;
        }
        if (g < 7) {
#pragma unroll
            for (int i = 0; i < 8; i++) cur[i] = nxt[i];
        }
    }
}

extern "C" void kernel_launch(void* const* d_in, const int* in_sizes, int n_in,
                              void* d_out, int out_size)
{
    const float* x  = (const float*)d_in[0];
    const float* la = (const float*)d_in[1];
    const float* lb = (const float*)d_in[2];
    float* out = (float*)d_out;

    dim3 grid(BB, NCH);
    k1_aggregate<<<grid, CC>>>(x, la, lb);
    k3_rescan<<<grid, CC>>>(x, la, lb, out);
}